// round 2
// baseline (speedup 1.0000x reference)
#include <cuda_runtime.h>
#include <math.h>

#define T_STEPS 12
#define NN      10000
#define NE      320000
#define IN_DIM  64
#define HID     128
#define EMB     64
#define G3      192             // 3*EMB
#define FTOT    (T_STEPS*EMB)   // 768 batched features
#define NROWS   (NN*T_STEPS)    // 120000

// ---------------- scratch (static device allocations only) ----------------
__device__ float d_dinv[NN];
__device__ int   d_cnt[NN];
__device__ int   d_off[NN+1];
__device__ int   d_fill[NN];
__device__ int   d_src[NE];
__device__ float d_w[NE];
__device__ float d_AX[(size_t)NN*FTOT];    // (ÂX) batched, [n][t*64+k]  (30MB)
__device__ float d_H1[(size_t)NROWS*HID];  // relu((ÂX)W1+b1)            (61MB)
__device__ float d_H2[(size_t)NROWS*EMB];  // H1@W2                      (30MB)
__device__ float d_Z [(size_t)NN*FTOT];    // z_seq, [n][t*64+k]         (30MB)
__device__ float d_h [(size_t)NN*EMB];     // GRU hidden
__device__ float d_WtIH[EMB*G3];           // W_ih transposed -> [k][3H]
__device__ float d_WtHH[EMB*G3];

// ---------------- preprocessing ----------------
__global__ void k_init() {
    int i = blockIdx.x*blockDim.x + threadIdx.x;
    if (i < NN*EMB) d_h[i] = 0.f;
    if (i < NN) { d_dinv[i] = 1.0f; d_cnt[i] = 0; }   // self-loop weight 1 pre-added to deg
}

__global__ void k_deg_hist(const int* __restrict__ ei, const float* __restrict__ ew) {
    int e = blockIdx.x*blockDim.x + threadIdx.x;
    if (e >= NE) return;
    int c = ei[NE + e];
    atomicAdd(&d_dinv[c], ew[e]);
    atomicAdd(&d_cnt[c], 1);
}

__global__ void k_rsqrt() {
    int i = blockIdx.x*blockDim.x + threadIdx.x;
    if (i < NN) d_dinv[i] = rsqrtf(d_dinv[i]);   // deg >= 1 always (self-loop)
}

// single-block exclusive scan of d_cnt -> d_off, copy into d_fill
__global__ void k_scan() {
    __shared__ int sh[1024];
    __shared__ int carry;
    int tid = threadIdx.x;
    if (tid == 0) carry = 0;
    __syncthreads();
    const int nch = (NN + 1023) / 1024;
    for (int c = 0; c < nch; c++) {
        int base = carry;
        int i = c*1024 + tid;
        int v = (i < NN) ? d_cnt[i] : 0;
        sh[tid] = v;
        __syncthreads();
        for (int ofs = 1; ofs < 1024; ofs <<= 1) {
            int t = (tid >= ofs) ? sh[tid-ofs] : 0;
            __syncthreads();
            sh[tid] += t;
            __syncthreads();
        }
        int excl = sh[tid] - v + base;
        if (i < NN) { d_off[i] = excl; d_fill[i] = excl; }
        __syncthreads();
        if (tid == 0) carry = base + sh[1023];
        __syncthreads();
    }
    if (tid == 0) d_off[NN] = carry;
}

__global__ void k_scatter(const int* __restrict__ ei, const float* __restrict__ ew) {
    int e = blockIdx.x*blockDim.x + threadIdx.x;
    if (e >= NE) return;
    int r = ei[e];
    int c = ei[NE + e];
    float nm = d_dinv[r] * ew[e] * d_dinv[c];
    int pos = atomicAdd(&d_fill[c], 1);
    d_src[pos] = r;
    d_w[pos]   = nm;
}

__global__ void k_transposeW(const float* __restrict__ W_ih, const float* __restrict__ W_hh) {
    int idx = blockIdx.x*blockDim.x + threadIdx.x;   // over G3*EMB
    if (idx >= G3*EMB) return;
    int j = idx >> 6, k = idx & 63;
    d_WtIH[k*G3 + j] = W_ih[idx];
    d_WtHH[k*G3 + j] = W_hh[idx];
}

// ---------------- batched SpMM: AX = Â X  (all 12 timesteps, 768 feats) ----------------
__global__ void k_spmmX(const float* __restrict__ X) {   // X = x_seq [T][N][64]
    int d = blockIdx.x;
    int j = blockIdx.y*256 + threadIdx.x;   // 0..767
    int t = j >> 6, k = j & 63;
    float di = d_dinv[d];
    float acc = di*di * X[(size_t)t*NN*IN_DIM + (size_t)d*IN_DIM + k];
    int beg = d_off[d], end = d_off[d+1];
    for (int p = beg; p < end; p++) {
        int s = d_src[p]; float w = d_w[p];
        acc += w * X[(size_t)t*NN*IN_DIM + (size_t)s*IN_DIM + k];
    }
    d_AX[(size_t)d*FTOT + j] = acc;
}

// ---------------- H1 = relu(AX @ W1 + b1), rows = 120000 ----------------
__global__ void k_gemm1(const float* __restrict__ W1, const float* __restrict__ b1) {
    __shared__ float xs[2][IN_DIM];
    int row = blockIdx.x*2 + threadIdx.y;
    int tx = threadIdx.x;
    if (tx < IN_DIM) xs[threadIdx.y][tx] = d_AX[(size_t)row*IN_DIM + tx];
    __syncthreads();
    float acc = 0.f;
    #pragma unroll
    for (int k = 0; k < IN_DIM; k++) acc += xs[threadIdx.y][k] * W1[k*HID + tx];
    d_H1[(size_t)row*HID + tx] = fmaxf(acc + b1[tx], 0.f);
}

// ---------------- H2 = H1 @ W2 ----------------
__global__ void k_gemm2(const float* __restrict__ W2) {
    __shared__ float as[4][HID];
    int base = blockIdx.x*4;
    int lid = threadIdx.y*64 + threadIdx.x;
    for (int idx = lid; idx < 4*HID; idx += 256)
        as[idx >> 7][idx & 127] = d_H1[(size_t)(base + (idx >> 7))*HID + (idx & 127)];
    __syncthreads();
    float acc = 0.f;
    #pragma unroll
    for (int k = 0; k < HID; k++) acc += as[threadIdx.y][k] * W2[k*EMB + threadIdx.x];
    d_H2[(size_t)(base + threadIdx.y)*EMB + threadIdx.x] = acc;
}

// ---------------- batched SpMM: Z = Â H2 + b2 ----------------
__global__ void k_spmmZ(const float* __restrict__ b2) {
    int d = blockIdx.x;
    int j = blockIdx.y*256 + threadIdx.x;
    float di = d_dinv[d];
    float acc = di*di * d_H2[(size_t)d*FTOT + j];
    int beg = d_off[d], end = d_off[d+1];
    for (int p = beg; p < end; p++) {
        int s = d_src[p]; float w = d_w[p];
        acc += w * d_H2[(size_t)s*FTOT + j];
    }
    d_Z[(size_t)d*FTOT + j] = acc + b2[j & 63];
}

// ---------------- GRU step (in-place on d_h) ----------------
__global__ void k_gru(int t, const float* __restrict__ b_ih, const float* __restrict__ b_hh) {
    __shared__ float xs[4][EMB], hs[4][EMB];
    int node = blockIdx.x*4 + threadIdx.y;
    int j = threadIdx.x;
    xs[threadIdx.y][j] = d_Z[(size_t)node*FTOT + t*EMB + j];
    hs[threadIdx.y][j] = d_h[(size_t)node*EMB + j];
    __syncthreads();
    float air=0.f, aiz=0.f, ain=0.f, ahr=0.f, ahz=0.f, ahn=0.f;
    #pragma unroll
    for (int k = 0; k < EMB; k++) {
        float xv = xs[threadIdx.y][k], hv = hs[threadIdx.y][k];
        const float* wi = &d_WtIH[k*G3];
        const float* wh = &d_WtHH[k*G3];
        air += xv*wi[j];      aiz += xv*wi[64+j];  ain += xv*wi[128+j];
        ahr += hv*wh[j];      ahz += hv*wh[64+j];  ahn += hv*wh[128+j];
    }
    float r  = 1.f/(1.f + expf(-(air + b_ih[j]     + ahr + b_hh[j])));
    float zg = 1.f/(1.f + expf(-(aiz + b_ih[64+j]  + ahz + b_hh[64+j])));
    float ng = tanhf(ain + b_ih[128+j] + r*(ahn + b_hh[128+j]));
    float hold = hs[threadIdx.y][j];
    d_h[(size_t)node*EMB + j] = (1.f - zg)*ng + zg*hold;
}

__global__ void k_copy_z(float* __restrict__ out) {
    int i = blockIdx.x*blockDim.x + threadIdx.x;
    if (i < NN*EMB) out[(size_t)NN*NN + i] = d_h[i];
}

// ---------------- decoder: out = softplus(z z^T + b), symmetric ----------------
__global__ void __launch_bounds__(256)
k_dec(float* __restrict__ out, const float* __restrict__ db) {
    int bi = blockIdx.y, bj = blockIdx.x;
    if (bi > bj) return;
    __shared__ __align__(16) float As[32][132];
    __shared__ __align__(16) float Bs[32][132];
    int tid = threadIdx.x;
    int tj = tid & 15, ti = tid >> 4;
    int i0 = bi*128, j0 = bj*128;
    float c[8][8];
    #pragma unroll
    for (int u = 0; u < 8; u++)
        #pragma unroll
        for (int v = 0; v < 8; v++) c[u][v] = 0.f;

    for (int kc = 0; kc < 2; kc++) {
        __syncthreads();
        for (int idx = tid; idx < 128*32; idx += 256) {
            int k = idx & 31, i = idx >> 5;
            int gi = i0 + i;
            As[k][i] = (gi < NN) ? d_h[(size_t)gi*EMB + kc*32 + k] : 0.f;
            int gj = j0 + i;
            Bs[k][i] = (gj < NN) ? d_h[(size_t)gj*EMB + kc*32 + k] : 0.f;
        }
        __syncthreads();
        #pragma unroll
        for (int k = 0; k < 32; k++) {
            float4 a0 = *(const float4*)&As[k][ti*8];
            float4 a1 = *(const float4*)&As[k][ti*8+4];
            float4 b0 = *(const float4*)&Bs[k][tj*8];
            float4 b1 = *(const float4*)&Bs[k][tj*8+4];
            float av[8] = {a0.x,a0.y,a0.z,a0.w,a1.x,a1.y,a1.z,a1.w};
            float bv[8] = {b0.x,b0.y,b0.z,b0.w,b1.x,b1.y,b1.z,b1.w};
            #pragma unroll
            for (int u = 0; u < 8; u++)
                #pragma unroll
                for (int v = 0; v < 8; v++) c[u][v] += av[u]*bv[v];
        }
    }

    float bias = db[0];
    #pragma unroll
    for (int u = 0; u < 8; u++)
        #pragma unroll
        for (int v = 0; v < 8; v++) {
            float x = c[u][v] + bias;
            c[u][v] = fmaxf(x, 0.f) + log1pf(expf(-fabsf(x)));   // softplus
        }

    bool edge = (i0 + 128 > NN) || (j0 + 128 > NN);
    // direct store
    #pragma unroll
    for (int u = 0; u < 8; u++) {
        int gi = i0 + ti*8 + u;
        if (gi >= NN) continue;
        if (!edge) {
            float4 s0 = make_float4(c[u][0], c[u][1], c[u][2], c[u][3]);
            float4 s1 = make_float4(c[u][4], c[u][5], c[u][6], c[u][7]);
            *(float4*)&out[(size_t)gi*NN + j0 + tj*8]     = s0;
            *(float4*)&out[(size_t)gi*NN + j0 + tj*8 + 4] = s1;
        } else {
            for (int v = 0; v < 8; v++) {
                int gj = j0 + tj*8 + v;
                if (gj < NN) out[(size_t)gi*NN + gj] = c[u][v];
            }
        }
    }
    // mirror store
    if (bi != bj) {
        #pragma unroll
        for (int v = 0; v < 8; v++) {
            int gj = j0 + tj*8 + v;
            if (gj >= NN) continue;
            if (!edge) {
                float4 s0 = make_float4(c[0][v], c[1][v], c[2][v], c[3][v]);
                float4 s1 = make_float4(c[4][v], c[5][v], c[6][v], c[7][v]);
                *(float4*)&out[(size_t)gj*NN + i0 + ti*8]     = s0;
                *(float4*)&out[(size_t)gj*NN + i0 + ti*8 + 4] = s1;
            } else {
                for (int u = 0; u < 8; u++) {
                    int gi = i0 + ti*8 + u;
                    if (gi < NN) out[(size_t)gj*NN + gi] = c[u][v];
                }
            }
        }
    }
}

// ---------------- launch ----------------
extern "C" void kernel_launch(void* const* d_in, const int* in_sizes, int n_in,
                              void* d_out, int out_size) {
    const float* x_seq = (const float*)d_in[0];
    const int*   ei    = (const int*)d_in[1];     // int32: jax demotes int64 by default
    const float* ew    = (const float*)d_in[2];
    const float* W1    = (const float*)d_in[3];
    const float* b1    = (const float*)d_in[4];
    const float* W2    = (const float*)d_in[5];
    const float* b2    = (const float*)d_in[6];
    const float* W_ih  = (const float*)d_in[7];
    const float* W_hh  = (const float*)d_in[8];
    const float* b_ih  = (const float*)d_in[9];
    const float* b_hh  = (const float*)d_in[10];
    const float* dbias = (const float*)d_in[11];
    float* out = (float*)d_out;

    // preprocessing
    k_init<<<(NN*EMB + 255)/256, 256>>>();
    k_deg_hist<<<(NE + 255)/256, 256>>>(ei, ew);
    k_rsqrt<<<(NN + 255)/256, 256>>>();
    k_scan<<<1, 1024>>>();
    k_scatter<<<(NE + 255)/256, 256>>>(ei, ew);
    k_transposeW<<<(G3*EMB + 255)/256, 256>>>(W_ih, W_hh);

    // encoder (batched across all 12 timesteps)
    k_spmmX<<<dim3(NN, FTOT/256), 256>>>(x_seq);
    k_gemm1<<<NROWS/2, dim3(HID, 2)>>>(W1, b1);
    k_gemm2<<<NROWS/4, dim3(EMB, 4)>>>(W2);
    k_spmmZ<<<dim3(NN, FTOT/256), 256>>>(b2);

    // GRU
    for (int t = 0; t < T_STEPS; t++)
        k_gru<<<NN/4, dim3(EMB, 4)>>>(t, b_ih, b_hh);

    k_copy_z<<<(NN*EMB + 255)/256, 256>>>(out);

    // decoder (symmetric)
    const int NT = (NN + 127)/128;   // 79
    k_dec<<<dim3(NT, NT), 256>>>(out, dbias);
}